// round 7
// baseline (speedup 1.0000x reference)
#include <cuda_runtime.h>
#include <math.h>

#define NEXP 16
#define MAX_T 4096
#define NBINS 256

// Scratch (allocation-free per harness rules)
__device__ float g_probs[NEXP * MAX_T];   // [e][t] for coalesced aux reduce
__device__ float g_s0[MAX_T];
__device__ float g_s1[MAX_T];
__device__ int   g_key[MAX_T];            // i0*16+i1 per token
__device__ int   g_sorted[MAX_T];         // token ids grouped by key
__device__ int   g_binStart[NBINS];
__device__ int   g_binCount[NBINS];

// ---------------------------------------------------------------------------
// Kernel 1: gating. One warp per 2 tokens, float4-vectorized, 128-thr blocks
// (256 blocks -> fills 148 SMs). gw (131KB) L1-resident via __ldg.
// ---------------------------------------------------------------------------
__global__ void gate_kernel(const float4* __restrict__ hs,
                            const float4* __restrict__ gw,
                            int T, int H4) {
    int warp = (blockIdx.x * blockDim.x + threadIdx.x) >> 5;
    int lane = threadIdx.x & 31;
    int t0 = warp * 2;
    if (t0 >= T) return;
    int t1 = t0 + 1;
    bool has1 = (t1 < T);

    const float4* hrow0 = hs + (size_t)t0 * H4;
    const float4* hrow1 = hs + (size_t)(has1 ? t1 : t0) * H4;

    float acc0[NEXP], acc1[NEXP];
#pragma unroll
    for (int e = 0; e < NEXP; e++) { acc0[e] = 0.f; acc1[e] = 0.f; }

    for (int h = lane; h < H4; h += 32) {
        float4 hv0 = hrow0[h];
        float4 hv1 = hrow1[h];
#pragma unroll
        for (int e = 0; e < NEXP; e++) {
            float4 w = __ldg(&gw[(size_t)e * H4 + h]);
            acc0[e] += fmaf(hv0.x, w.x, hv0.y * w.y)
                     + fmaf(hv0.z, w.z, hv0.w * w.w);
            acc1[e] += fmaf(hv1.x, w.x, hv1.y * w.y)
                     + fmaf(hv1.z, w.z, hv1.w * w.w);
        }
    }

#pragma unroll
    for (int e = 0; e < NEXP; e++) {
#pragma unroll
        for (int off = 16; off; off >>= 1) {
            acc0[e] += __shfl_xor_sync(0xffffffffu, acc0[e], off);
            acc1[e] += __shfl_xor_sync(0xffffffffu, acc1[e], off);
        }
    }

    if (lane == 0) {
#pragma unroll
        for (int which = 0; which < 2; which++) {
            if (which == 1 && !has1) break;
            int tk = t0 + which;
            float* acc = which ? acc1 : acc0;

            float m = acc[0];
#pragma unroll
            for (int e = 1; e < NEXP; e++) m = fmaxf(m, acc[e]);
            float p[NEXP];
            float sum = 0.f;
#pragma unroll
            for (int e = 0; e < NEXP; e++) { p[e] = __expf(acc[e] - m); sum += p[e]; }
            float inv = 1.f / sum;
#pragma unroll
            for (int e = 0; e < NEXP; e++) {
                p[e] *= inv;
                g_probs[e * MAX_T + tk] = p[e];
            }
            // top-2 (lowest index wins ties, matching lax.top_k)
            float b0 = -1.f, b1 = -1.f;
            int   bi0 = 0,   bi1 = 0;
#pragma unroll
            for (int e = 0; e < NEXP; e++) {
                if (p[e] > b0)      { b1 = b0; bi1 = bi0; b0 = p[e]; bi0 = e; }
                else if (p[e] > b1) { b1 = p[e]; bi1 = e; }
            }
            float s = 1.f / (b0 + b1);
            g_s0[tk] = b0 * s;
            g_s1[tk] = b1 * s;
            g_key[tk] = bi0 * NEXP + bi1;
        }
    }
}

// ---------------------------------------------------------------------------
// Kernel 2: counting-sort tokens by expert-pair key. Single block; all state
// in smem (fresh each graph replay -> deterministic). Order within a bin is
// atomic-nondeterministic but bias output is order-invariant.
// ---------------------------------------------------------------------------
__global__ void sort_kernel(int T) {
    __shared__ int hist[NBINS];
    __shared__ int start[NBINS];
    __shared__ int cursor[NBINS];
    int tid = threadIdx.x;                       // 1024 threads

    if (tid < NBINS) hist[tid] = 0;
    __syncthreads();

    for (int t = tid; t < T; t += blockDim.x)
        atomicAdd(&hist[g_key[t]], 1);
    __syncthreads();

    if (tid == 0) {
        int acc = 0;
        for (int b = 0; b < NBINS; b++) {
            start[b] = acc;
            acc += hist[b];
        }
    }
    __syncthreads();
    if (tid < NBINS) {
        cursor[tid] = start[tid];
        g_binStart[tid] = start[tid];
        g_binCount[tid] = hist[tid];
    }
    __syncthreads();

    for (int t = tid; t < T; t += blockDim.x) {
        int pos = atomicAdd(&cursor[g_key[t]], 1);
        g_sorted[pos] = t;
    }
}

// ---------------------------------------------------------------------------
// Kernel 3: bias. grid = (V chunks, 256 bins). Block loads its two expert
// chunks into REGISTERS once, then loops over its bin's tokens doing only
// FFMA + streaming stores -> L2 reads ~64MB (was 524MB); pure DRAM-write
// bound. Aux loss fused into block (0,0) (bin 0 = key 0 is impossible, so
// that block otherwise exits immediately).
// ---------------------------------------------------------------------------
__global__ void bias_kernel(const float* __restrict__ eb,
                            float* __restrict__ out,
                            int T, int V, int has_aux) {
    const int bin = blockIdx.y;

    if (has_aux && blockIdx.x == 0 && bin == 0) {
        __shared__ float su[NEXP];
        int w = threadIdx.x >> 5, lane = threadIdx.x & 31;   // 8 warps
#pragma unroll
        for (int half = 0; half < 2; half++) {
            int e = w + half * 8;
            float s = 0.f;
            for (int t = lane; t < T; t += 32)
                s += g_probs[e * MAX_T + t];
#pragma unroll
            for (int off = 16; off; off >>= 1)
                s += __shfl_xor_sync(0xffffffffu, s, off);
            if (lane == 0) su[e] = s / (float)T;
        }
        __syncthreads();
        if (threadIdx.x == 0) {
            float a = 0.f;
#pragma unroll
            for (int i = 0; i < NEXP; i++)
                a += su[i] * logf(su[i]);
            out[(size_t)T * V] = a * (float)NEXP;
        }
    }

    const int count = g_binCount[bin];
    if (count == 0) return;
    const int startp = g_binStart[bin];
    const int e0 = bin >> 4;
    const int e1 = bin & 15;

    const int V4 = V >> 2;
    const int vA = blockIdx.x * (blockDim.x * 2) + threadIdx.x;
    const int vB = vA + blockDim.x;
    const bool hasA = (vA < V4);
    const bool hasB = (vB < V4);

    // Load both experts' chunk slices into registers ONCE.
    float4 a0, a1, b0, b1;
    const float4* r0 = (const float4*)(eb + (size_t)e0 * V);
    const float4* r1 = (const float4*)(eb + (size_t)e1 * V);
    if (hasA) { a0 = __ldg(&r0[vA]); b0 = __ldg(&r1[vA]); }
    if (hasB) { a1 = __ldg(&r0[vB]); b1 = __ldg(&r1[vB]); }

    for (int i = 0; i < count; i++) {
        int t = g_sorted[startp + i];          // broadcast load
        float s0 = g_s0[t];
        float s1 = g_s1[t];
        float4* o = (float4*)(out + (size_t)t * V);
        if (hasA) {
            float4 v;
            v.x = fmaf(s0, a0.x, s1 * b0.x);
            v.y = fmaf(s0, a0.y, s1 * b0.y);
            v.z = fmaf(s0, a0.z, s1 * b0.z);
            v.w = fmaf(s0, a0.w, s1 * b0.w);
            __stcs(&o[vA], v);
        }
        if (hasB) {
            float4 v;
            v.x = fmaf(s0, a1.x, s1 * b1.x);
            v.y = fmaf(s0, a1.y, s1 * b1.y);
            v.z = fmaf(s0, a1.z, s1 * b1.z);
            v.w = fmaf(s0, a1.w, s1 * b1.w);
            __stcs(&o[vB], v);
        }
    }
}

extern "C" void kernel_launch(void* const* d_in, const int* in_sizes, int n_in,
                              void* d_out, int out_size) {
    const float* hs = (const float*)d_in[0];  // (T, H)
    const float* gw = (const float*)d_in[1];  // (E, H)
    const float* eb = (const float*)d_in[2];  // (E, V)
    float* out = (float*)d_out;

    int H = in_sizes[1] / NEXP;
    int T = in_sizes[0] / H;
    int V = in_sizes[2] / NEXP;
    int H4 = H >> 2;

    // 1. gating: one warp per 2 tokens, 128-thread blocks -> 256 blocks
    {
        int nwarps = (T + 1) / 2;
        int threads = 128;
        int blocks = (nwarps * 32 + threads - 1) / threads;
        gate_kernel<<<blocks, threads>>>((const float4*)hs, (const float4*)gw,
                                         T, H4);
    }

    // 2. counting sort by expert pair
    sort_kernel<<<1, 1024>>>(T);

    // 3. bias (+fused aux): grid = (V chunks, 256 bins), 2 float4/thread
    {
        long long tv = (long long)T * (long long)V;
        int has_aux = ((long long)out_size > tv) ? 1 : 0;
        int V4 = V >> 2;
        int threads = 256;
        int bx = (V4 + threads * 2 - 1) / (threads * 2);
        dim3 grid(bx, NBINS);
        bias_kernel<<<grid, threads>>>(eb, out, T, V, has_aux);
    }
}

// round 8
// speedup vs baseline: 1.0152x; 1.0152x over previous
#include <cuda_runtime.h>
#include <math.h>

#define NEXP 16
#define MAX_T 4096
#define NBINS 256

// Scratch (allocation-free per harness rules)
__device__ float g_probs[NEXP * MAX_T];   // [e][t] for coalesced aux reduce
__device__ float g_s0[MAX_T];
__device__ float g_s1[MAX_T];
__device__ int   g_key[MAX_T];            // i0*16+i1 per token
__device__ int   g_sorted[MAX_T];         // token ids grouped by key
__device__ int   g_binStart[NBINS];
__device__ int   g_binCount[NBINS];

// ---------------------------------------------------------------------------
// Kernel 1: gating. One warp per token, 256-thread blocks (grid=T/8 blocks,
// 2048 warps ~ 14/SM), float4 + manual 2x h-unroll for MLP.
// gw (131KB) L1-resident via __ldg; hs streamed with __ldcs.
// ---------------------------------------------------------------------------
__global__ void gate_kernel(const float4* __restrict__ hs,
                            const float4* __restrict__ gw,
                            int T, int H4) {
    int warp = (blockIdx.x * blockDim.x + threadIdx.x) >> 5;
    int lane = threadIdx.x & 31;
    if (warp >= T) return;

    const float4* hrow = hs + (size_t)warp * H4;
    float acc[NEXP];
#pragma unroll
    for (int e = 0; e < NEXP; e++) acc[e] = 0.f;

    // H4 = 512 -> 8 iterations of 2 independent h-positions
    for (int h = lane; h + 32 < H4; h += 64) {
        float4 hv0 = __ldcs(&hrow[h]);
        float4 hv1 = __ldcs(&hrow[h + 32]);
#pragma unroll
        for (int e = 0; e < NEXP; e++) {
            float4 w0 = __ldg(&gw[(size_t)e * H4 + h]);
            float4 w1 = __ldg(&gw[(size_t)e * H4 + h + 32]);
            float p0 = fmaf(hv0.x, w0.x, hv0.y * w0.y)
                     + fmaf(hv0.z, w0.z, hv0.w * w0.w);
            float p1 = fmaf(hv1.x, w1.x, hv1.y * w1.y)
                     + fmaf(hv1.z, w1.z, hv1.w * w1.w);
            acc[e] += p0 + p1;
        }
    }
    // tail (only if H4/32 is odd)
    if ((H4 >> 5) & 1) {
        int h = (H4 - 32) + lane - 31 + 31;    // last stripe start + lane
        h = ((H4 >> 5) - 1) * 32 + lane;
        float4 hv = __ldcs(&hrow[h]);
#pragma unroll
        for (int e = 0; e < NEXP; e++) {
            float4 w = __ldg(&gw[(size_t)e * H4 + h]);
            acc[e] += fmaf(hv.x, w.x, hv.y * w.y)
                    + fmaf(hv.z, w.z, hv.w * w.w);
        }
    }

#pragma unroll
    for (int e = 0; e < NEXP; e++) {
#pragma unroll
        for (int off = 16; off; off >>= 1)
            acc[e] += __shfl_xor_sync(0xffffffffu, acc[e], off);
    }

    if (lane == 0) {
        float m = acc[0];
#pragma unroll
        for (int e = 1; e < NEXP; e++) m = fmaxf(m, acc[e]);
        float p[NEXP];
        float sum = 0.f;
#pragma unroll
        for (int e = 0; e < NEXP; e++) { p[e] = __expf(acc[e] - m); sum += p[e]; }
        float inv = 1.f / sum;
#pragma unroll
        for (int e = 0; e < NEXP; e++) {
            p[e] *= inv;
            g_probs[e * MAX_T + warp] = p[e];
        }
        // top-2 (lowest index wins ties, matching lax.top_k)
        float b0 = -1.f, b1 = -1.f;
        int   bi0 = 0,   bi1 = 0;
#pragma unroll
        for (int e = 0; e < NEXP; e++) {
            if (p[e] > b0)      { b1 = b0; bi1 = bi0; b0 = p[e]; bi0 = e; }
            else if (p[e] > b1) { b1 = p[e]; bi1 = e; }
        }
        float s = 1.f / (b0 + b1);
        g_s0[warp] = b0 * s;
        g_s1[warp] = b1 * s;
        g_key[warp] = bi0 * NEXP + bi1;
    }
}

// ---------------------------------------------------------------------------
// Kernel 2: counting-sort tokens by expert-pair key. Single block; all state
// in smem (fresh each graph replay -> deterministic). Order within a bin is
// atomic-nondeterministic but bias output is order-invariant.
// ---------------------------------------------------------------------------
__global__ void sort_kernel(int T) {
    __shared__ int hist[NBINS];
    __shared__ int start[NBINS];
    __shared__ int cursor[NBINS];
    int tid = threadIdx.x;                       // 1024 threads

    if (tid < NBINS) hist[tid] = 0;
    __syncthreads();

    for (int t = tid; t < T; t += blockDim.x)
        atomicAdd(&hist[g_key[t]], 1);
    __syncthreads();

    if (tid == 0) {
        int acc = 0;
        for (int b = 0; b < NBINS; b++) {
            start[b] = acc;
            acc += hist[b];
        }
    }
    __syncthreads();
    if (tid < NBINS) {
        cursor[tid] = start[tid];
        g_binStart[tid] = start[tid];
        g_binCount[tid] = hist[tid];
    }
    __syncthreads();

    for (int t = tid; t < T; t += blockDim.x) {
        int pos = atomicAdd(&cursor[g_key[t]], 1);
        g_sorted[pos] = t;
    }
}

// ---------------------------------------------------------------------------
// Kernel 3: bias. grid = (V chunks, 256 bins). Block loads its two expert
// chunks into REGISTERS once, then loops over its bin's tokens doing only
// FFMA + streaming stores -> L2 reads ~64MB; pure DRAM-write bound.
// Aux loss fused into block (0,0) (bin 0 = key 0 is impossible, so that
// block otherwise exits immediately).
// ---------------------------------------------------------------------------
__global__ void bias_kernel(const float* __restrict__ eb,
                            float* __restrict__ out,
                            int T, int V, int has_aux) {
    const int bin = blockIdx.y;

    if (has_aux && blockIdx.x == 0 && bin == 0) {
        __shared__ float su[NEXP];
        int w = threadIdx.x >> 5, lane = threadIdx.x & 31;   // 8 warps
#pragma unroll
        for (int half = 0; half < 2; half++) {
            int e = w + half * 8;
            float s = 0.f;
            for (int t = lane; t < T; t += 32)
                s += g_probs[e * MAX_T + t];
#pragma unroll
            for (int off = 16; off; off >>= 1)
                s += __shfl_xor_sync(0xffffffffu, s, off);
            if (lane == 0) su[e] = s / (float)T;
        }
        __syncthreads();
        if (threadIdx.x == 0) {
            float a = 0.f;
#pragma unroll
            for (int i = 0; i < NEXP; i++)
                a += su[i] * logf(su[i]);
            out[(size_t)T * V] = a * (float)NEXP;
        }
    }

    const int count = g_binCount[bin];
    if (count == 0) return;
    const int startp = g_binStart[bin];
    const int e0 = bin >> 4;
    const int e1 = bin & 15;

    const int V4 = V >> 2;
    const int vA = blockIdx.x * (blockDim.x * 2) + threadIdx.x;
    const int vB = vA + blockDim.x;
    const bool hasA = (vA < V4);
    const bool hasB = (vB < V4);

    // Load both experts' chunk slices into registers ONCE.
    float4 a0, a1, b0, b1;
    const float4* r0 = (const float4*)(eb + (size_t)e0 * V);
    const float4* r1 = (const float4*)(eb + (size_t)e1 * V);
    if (hasA) { a0 = __ldg(&r0[vA]); b0 = __ldg(&r1[vA]); }
    if (hasB) { a1 = __ldg(&r0[vB]); b1 = __ldg(&r1[vB]); }

    for (int i = 0; i < count; i++) {
        int t = g_sorted[startp + i];          // broadcast load
        float s0 = g_s0[t];
        float s1 = g_s1[t];
        float4* o = (float4*)(out + (size_t)t * V);
        if (hasA) {
            float4 v;
            v.x = fmaf(s0, a0.x, s1 * b0.x);
            v.y = fmaf(s0, a0.y, s1 * b0.y);
            v.z = fmaf(s0, a0.z, s1 * b0.z);
            v.w = fmaf(s0, a0.w, s1 * b0.w);
            __stcs(&o[vA], v);
        }
        if (hasB) {
            float4 v;
            v.x = fmaf(s0, a1.x, s1 * b1.x);
            v.y = fmaf(s0, a1.y, s1 * b1.y);
            v.z = fmaf(s0, a1.z, s1 * b1.z);
            v.w = fmaf(s0, a1.w, s1 * b1.w);
            __stcs(&o[vB], v);
        }
    }
}

extern "C" void kernel_launch(void* const* d_in, const int* in_sizes, int n_in,
                              void* d_out, int out_size) {
    const float* hs = (const float*)d_in[0];  // (T, H)
    const float* gw = (const float*)d_in[1];  // (E, H)
    const float* eb = (const float*)d_in[2];  // (E, V)
    float* out = (float*)d_out;

    int H = in_sizes[1] / NEXP;
    int T = in_sizes[0] / H;
    int V = in_sizes[2] / NEXP;
    int H4 = H >> 2;

    // 1. gating: one warp per token, 256-thread blocks -> grid 256
    {
        int threads = 256;
        int blocks = (T * 32 + threads - 1) / threads;
        gate_kernel<<<blocks, threads>>>((const float4*)hs, (const float4*)gw,
                                         T, H4);
    }

    // 2. counting sort by expert pair
    sort_kernel<<<1, 1024>>>(T);

    // 3. bias (+fused aux): grid = (V chunks, 256 bins), 2 float4/thread
    {
        long long tv = (long long)T * (long long)V;
        int has_aux = ((long long)out_size > tv) ? 1 : 0;
        int V4 = V >> 2;
        int threads = 256;
        int bx = (V4 + threads * 2 - 1) / (threads * 2);
        dim3 grid(bx, NBINS);
        bias_kernel<<<grid, threads>>>(eb, out, T, V, has_aux);
    }
}